// round 11
// baseline (speedup 1.0000x reference)
#include <cuda_runtime.h>
#include <cuda_fp16.h>

// SegmentationLoss: ce(ignore=255, mean over valid) + 0.5 * dice
// pred [4,172,256,256] f32, target [4,256,256] i32 -> scalar f32
//
// v5 = v2 (72us, proven) with EXACTLY ONE change: pass 2 is a transposed
// reduction (warp owns channel-pairs, lanes sum pixels, 1 butterfly per
// channel-pair -> 55 SHFLs/warp instead of 430). Pass 1, tile layout,
// 3-kernel structure all byte-identical to v2.

#define NC   172
#define NCP  (NC/2)             // 86 channel pairs
#define HW   65536
#define NPIX (4 * HW)           // 262144
#define TPB  256
#define NBLK (NPIX / TPB)       // 1024
#define IGN  255
#define EPSF 1e-7f

__device__ float g_union[NC];
__device__ float g_inter[NC];
__device__ float g_counts[NC];
__device__ float g_nll;
__device__ float g_valid;

__global__ void seg_zero() {
    int t = threadIdx.x;
    if (t < NC) { g_union[t] = 0.f; g_inter[t] = 0.f; g_counts[t] = 0.f; }
    if (t == NC) { g_nll = 0.f; g_valid = 0.f; }
}

__device__ __forceinline__ unsigned short pack_e4m3(float hi, float lo) {
    unsigned short r;
    asm("cvt.rn.satfinite.e4m3x2.f32 %0, %1, %2;" : "=h"(r) : "f"(hi), "f"(lo));
    return r;   // byte0 = lo, byte1 = hi
}
__device__ __forceinline__ __half2 unpack_e4m3(unsigned short v) {
    unsigned u;
    asm("cvt.rn.f16x2.e4m3x2 %0, %1;" : "=r"(u) : "h"(v));
    __half2 h;
    *reinterpret_cast<unsigned*>(&h) = u;   // lo half = byte0
    return h;
}
__device__ __forceinline__ __half2 h2_bfly_add(__half2 x, int o) {
    unsigned u = __shfl_xor_sync(0xffffffffu, *reinterpret_cast<unsigned*>(&x), o);
    return __hadd2(x, *reinterpret_cast<__half2*>(&u));
}

extern __shared__ unsigned char smem_raw[];

__global__ __launch_bounds__(TPB, 4)
void seg_main(const float* __restrict__ pred, const int* __restrict__ target) {
    // shared layout:
    //   tile16 : NCP*TPB u16  (fp8 pair stash, [cp*TPB + pixel])  44032 B
    //   sinv2  : TPB half2    (per-pixel 1/s)                      1024 B
    //   inter_s: NC f32, cnt_s: NC f32 (target-scattered atomics)
    //   red    : 16 f32
    unsigned short* tile16 = (unsigned short*)smem_raw;
    __half2* sinv2  = (__half2*)(smem_raw + (size_t)NCP * TPB * sizeof(unsigned short));
    float* inter_s  = (float*)(smem_raw + 45056);
    float* cnt_s    = inter_s + NC;
    float* red      = cnt_s + NC;

    const int tid  = threadIdx.x;
    const int warp = tid >> 5;
    const int lane = tid & 31;

    for (int i = tid; i < NC; i += TPB) { inter_s[i] = 0.f; cnt_s[i] = 0.f; }
    __syncthreads();

    const int pix0 = blockIdx.x * TPB;          // 65536 % 256 == 0 -> never crosses batch
    const int b    = pix0 >> 16;
    const int hw   = pix0 & (HW - 1);
    const float* ptr = pred + (size_t)b * NC * HW + hw + tid;

    const int  tgt   = target[pix0 + tid];
    const bool valid = (tgt != IGN);

    // ---- pass 1: stream DRAM in batches of 8, exp, sum, stash fp8 pairs ----
    // (byte-identical to v2)
    float s = 0.f, xt = 0.f;
    #pragma unroll 1
    for (int i = 0; i < 21; i++) {              // 21*8 = 168 channels
        float x[8];
        #pragma unroll
        for (int j = 0; j < 8; j++) x[j] = __ldg(ptr + (size_t)j * HW);
        ptr += (size_t)8 * HW;
        float e[8];
        #pragma unroll
        for (int j = 0; j < 8; j++) {
            e[j] = __expf(x[j]);
            s += e[j];
            if (i * 8 + j == tgt) xt = x[j];
        }
        const int cp = i * 4;
        #pragma unroll
        for (int jp = 0; jp < 4; jp++)
            tile16[(cp + jp) * TPB + tid] = pack_e4m3(e[2*jp+1], e[2*jp]);
    }
    {   // tail: channels 168..171
        float x[4];
        #pragma unroll
        for (int j = 0; j < 4; j++) x[j] = __ldg(ptr + (size_t)j * HW);
        float e[4];
        #pragma unroll
        for (int j = 0; j < 4; j++) {
            e[j] = __expf(x[j]);
            s += e[j];
            if (168 + j == tgt) xt = x[j];
        }
        tile16[84 * TPB + tid] = pack_e4m3(e[1], e[0]);
        tile16[85 * TPB + tid] = pack_e4m3(e[3], e[2]);
    }

    const float inv_s = 1.f / s;
    sinv2[tid] = __float2half2_rn(inv_s);

    float nll = valid ? (__logf(s) - xt) : 0.f;
    float vv  = valid ? 1.f : 0.f;

    if (valid) {
        float pt = __expf(xt) * inv_s;          // p at target (fp32 path, exact)
        atomicAdd(&inter_s[tgt], pt);
        atomicAdd(&cnt_s[tgt], 1.f);
    }

    // block-reduce nll & valid count
    #pragma unroll
    for (int o = 16; o; o >>= 1) {
        nll += __shfl_xor_sync(0xffffffffu, nll, o);
        vv  += __shfl_xor_sync(0xffffffffu, vv,  o);
    }
    if (lane == 0) { red[warp] = nll; red[8 + warp] = vv; }

    __syncthreads();    // tile16 / sinv2 complete

    // ---- pass 2 (THE change): transposed union reduction ----
    // warp owns cp = warp, warp+8, ...; lanes sum 8 pixels each; one
    // butterfly per channel-pair. inv_s cached in registers, reused
    // across all of this warp's channel-pairs.
    __half2 iv[8];
    #pragma unroll
    for (int r = 0; r < 8; r++) iv[r] = sinv2[lane + 32 * r];

    const __half2 hz = __float2half2_rn(0.f);
    for (int cp = warp; cp < NCP; cp += 8) {
        const unsigned short* rowp = tile16 + cp * TPB + lane;
        __half2 a = hz;
        #pragma unroll
        for (int r = 0; r < 8; r++)
            a = __hfma2(unpack_e4m3(rowp[32 * r]), iv[r], a);
        #pragma unroll
        for (int o = 16; o; o >>= 1) a = h2_bfly_add(a, o);
        if (lane == 0) {
            float2 f = __half22float2(a);
            atomicAdd(&g_union[2 * cp],     f.x);
            atomicAdd(&g_union[2 * cp + 1], f.y);
        }
    }

    __syncthreads();

    // ---- fold remaining block partials into global accumulators ----
    if (tid < NC) {
        float iv2 = inter_s[tid]; if (iv2 != 0.f) atomicAdd(&g_inter[tid], iv2);
        float cv  = cnt_s[tid];   if (cv  != 0.f) atomicAdd(&g_counts[tid], cv);
    } else if (tid == NC) {
        float n = 0.f, v = 0.f;
        #pragma unroll
        for (int w = 0; w < 8; w++) { n += red[w]; v += red[8 + w]; }
        atomicAdd(&g_nll, n);
        atomicAdd(&g_valid, v);
    }
}

__global__ void seg_final(float* __restrict__ out) {
    __shared__ float sh_d[8], sh_n[8];
    const int tid  = threadIdx.x;   // 256
    const int warp = tid >> 5;
    const int lane = tid & 31;

    float d = 0.f, n = 0.f;
    if (tid < NC) {
        float uni = g_union[tid] + g_counts[tid];
        if (uni > 0.f) {
            d = (2.f * g_inter[tid] + EPSF) / (uni + EPSF);
            n = 1.f;
        }
    }
    #pragma unroll
    for (int o = 16; o; o >>= 1) {
        d += __shfl_xor_sync(0xffffffffu, d, o);
        n += __shfl_xor_sync(0xffffffffu, n, o);
    }
    if (lane == 0) { sh_d[warp] = d; sh_n[warp] = n; }
    __syncthreads();

    if (tid == 0) {
        float dt = 0.f, nt = 0.f;
        #pragma unroll
        for (int w = 0; w < 8; w++) { dt += sh_d[w]; nt += sh_n[w]; }
        float ce   = g_nll / fmaxf(g_valid, 1.f);
        float dice = (nt > 0.f) ? (1.f - dt / fmaxf(nt, 1.f)) : 0.f;
        out[0] = ce + 0.5f * dice;
    }
}

extern "C" void kernel_launch(void* const* d_in, const int* in_sizes, int n_in,
                              void* d_out, int out_size) {
    const float* pred   = (const float*)d_in[0];
    const int*   target = (const int*)d_in[1];
    float*       out    = (float*)d_out;

    // tile 44032 + sinv2 1024 + inter 688 + cnt 688 + red 64  (offsets fixed)
    const size_t smem = 45056 + (size_t)(NC + NC + 16) * sizeof(float); // 46,496 B
    cudaFuncSetAttribute(seg_main, cudaFuncAttributeMaxDynamicSharedMemorySize, (int)smem);

    seg_zero<<<1, 256>>>();
    seg_main<<<NBLK, TPB, smem>>>(pred, target);
    seg_final<<<1, 256>>>(out);
}

// round 12
// speedup vs baseline: 1.4361x; 1.4361x over previous
#include <cuda_runtime.h>
#include <cuda_fp16.h>

// SegmentationLoss: ce(ignore=255, mean over valid) + 0.5 * dice
// pred [4,172,256,256] f32, target [4,256,256] i32 -> scalar f32
//
// v6 = v2 (72us, best) with EXACTLY ONE change: the seg_zero / seg_final
// kernels are fused into seg_main via a last-CTA ticket finisher
// (validated in v3/v4; their regression is now attributed to the
// transposed pass-2, which is reverted here). Pass 1 and pass 2 are
// byte-identical to v2.

#define NC   172
#define NCP  (NC/2)             // 86 channel pairs
#define HW   65536
#define NPIX (4 * HW)           // 262144
#define TPB  256
#define NBLK (NPIX / TPB)       // 1024
#define IGN  255
#define EPSF 1e-7f

// smem byte offsets
#define OFF_TILE   0            // NCP*TPB u16 = 44032
#define OFF_USUM   44032        // 8*NC f32    = 5504
#define OFF_INTER  49536        // NC f32      = 688
#define OFF_CNT    50224        // NC f32      = 688
#define OFF_RED    50912        // 16 f32      = 64
#define OFF_LAST   50976        // int
#define SMEM_TOT   50980

__device__ float g_union[NC];
__device__ float g_inter[NC];
__device__ float g_counts[NC];
__device__ float g_nll;
__device__ float g_valid;
__device__ int   g_ticket;      // zero-init; finisher resets every launch

__device__ __forceinline__ unsigned short pack_e4m3(float hi, float lo) {
    unsigned short r;
    asm("cvt.rn.satfinite.e4m3x2.f32 %0, %1, %2;" : "=h"(r) : "f"(hi), "f"(lo));
    return r;   // byte0 = lo, byte1 = hi
}
__device__ __forceinline__ __half2 unpack_e4m3(unsigned short v) {
    unsigned u;
    asm("cvt.rn.f16x2.e4m3x2 %0, %1;" : "=r"(u) : "h"(v));
    __half2 h;
    *reinterpret_cast<unsigned*>(&h) = u;   // lo half = byte0
    return h;
}

extern __shared__ unsigned char smem_raw[];

__global__ __launch_bounds__(TPB, 4)
void seg_fused(const float* __restrict__ pred, const int* __restrict__ target,
               float* __restrict__ out) {
    unsigned short* tile16 = (unsigned short*)(smem_raw + OFF_TILE);
    float* usum    = (float*)(smem_raw + OFF_USUM);
    float* inter_s = (float*)(smem_raw + OFF_INTER);
    float* cnt_s   = (float*)(smem_raw + OFF_CNT);
    float* red     = (float*)(smem_raw + OFF_RED);
    int*   s_last  = (int*)(smem_raw + OFF_LAST);

    const int tid  = threadIdx.x;
    const int warp = tid >> 5;
    const int lane = tid & 31;

    for (int i = tid; i < NC; i += TPB) { inter_s[i] = 0.f; cnt_s[i] = 0.f; }
    __syncthreads();

    const int pix0 = blockIdx.x * TPB;          // 65536 % 256 == 0 -> never crosses batch
    const int b    = pix0 >> 16;
    const int hw   = pix0 & (HW - 1);
    const float* ptr = pred + (size_t)b * NC * HW + hw + tid;

    const int  tgt   = target[pix0 + tid];
    const bool valid = (tgt != IGN);

    // ---- pass 1 (byte-identical to v2): 8-wide batches, exp, sum, fp8 stash ----
    float s = 0.f, xt = 0.f;
    #pragma unroll 1
    for (int i = 0; i < 21; i++) {              // 21*8 = 168 channels
        float x[8];
        #pragma unroll
        for (int j = 0; j < 8; j++) x[j] = __ldg(ptr + (size_t)j * HW);
        ptr += (size_t)8 * HW;
        float e[8];
        #pragma unroll
        for (int j = 0; j < 8; j++) {
            e[j] = __expf(x[j]);
            s += e[j];
            if (i * 8 + j == tgt) xt = x[j];
        }
        const int cp = i * 4;
        #pragma unroll
        for (int jp = 0; jp < 4; jp++)
            tile16[(cp + jp) * TPB + tid] = pack_e4m3(e[2*jp+1], e[2*jp]);
    }
    {   // tail: channels 168..171
        float x[4];
        #pragma unroll
        for (int j = 0; j < 4; j++) x[j] = __ldg(ptr + (size_t)j * HW);
        float e[4];
        #pragma unroll
        for (int j = 0; j < 4; j++) {
            e[j] = __expf(x[j]);
            s += e[j];
            if (168 + j == tgt) xt = x[j];
        }
        tile16[84 * TPB + tid] = pack_e4m3(e[1], e[0]);
        tile16[85 * TPB + tid] = pack_e4m3(e[3], e[2]);
    }

    const float inv_s = 1.f / s;
    float nll = valid ? (__logf(s) - xt) : 0.f;
    float vv  = valid ? 1.f : 0.f;

    if (valid) {
        float pt = __expf(xt) * inv_s;          // p at target (fp32 path, exact)
        atomicAdd(&inter_s[tgt], pt);
        atomicAdd(&cnt_s[tgt], 1.f);
    }

    // block-reduce nll & valid count
    #pragma unroll
    for (int o = 16; o; o >>= 1) {
        nll += __shfl_xor_sync(0xffffffffu, nll, o);
        vv  += __shfl_xor_sync(0xffffffffu, vv,  o);
    }
    if (lane == 0) { red[warp] = nll; red[8 + warp] = vv; }

    // ---- pass 2 (byte-identical to v2): per-channel-pair butterflies ----
    const __half2 inv2 = __float2half2_rn(inv_s);
    #pragma unroll 2
    for (int cp = 0; cp < NCP; cp++) {
        __half2 p2 = __hmul2(unpack_e4m3(tile16[cp * TPB + tid]), inv2);
        #pragma unroll
        for (int o = 16; o; o >>= 1) {
            unsigned u = __shfl_xor_sync(0xffffffffu, *reinterpret_cast<unsigned*>(&p2), o);
            p2 = __hadd2(p2, *reinterpret_cast<__half2*>(&u));
        }
        if (lane == 0) {
            float2 f = __half22float2(p2);
            usum[warp * NC + 2*cp]     = f.x;
            usum[warp * NC + 2*cp + 1] = f.y;
        }
    }
    __syncthreads();

    // ---- fold block partials into global accumulators (v2 fold) ----
    if (tid < NC) {
        float u = 0.f;
        #pragma unroll
        for (int w = 0; w < 8; w++) u += usum[w * NC + tid];
        atomicAdd(&g_union[tid], u);
        float iv = inter_s[tid];
        if (iv != 0.f) atomicAdd(&g_inter[tid], iv);
        float cv = cnt_s[tid];
        if (cv != 0.f) atomicAdd(&g_counts[tid], cv);
    } else if (tid == NC) {
        float n = 0.f, v = 0.f;
        #pragma unroll
        for (int w = 0; w < 8; w++) { n += red[w]; v += red[8 + w]; }
        atomicAdd(&g_nll, n);
        atomicAdd(&g_valid, v);
    }

    // ---- last-CTA finisher (THE change vs v2; validated in v3/v4) ----
    __threadfence();
    __syncthreads();
    if (tid == 0) {
        int old = atomicAdd(&g_ticket, 1);
        *s_last = (old == NBLK - 1);
    }
    __syncthreads();
    if (*s_last) {
        __threadfence();    // acquire: all blocks' atomics visible
        float d = 0.f, n = 0.f;
        if (tid < NC) {
            float uni = g_union[tid] + g_counts[tid];
            if (uni > 0.f) { d = (2.f * g_inter[tid] + EPSF) / (uni + EPSF); n = 1.f; }
        }
        #pragma unroll
        for (int o = 16; o; o >>= 1) {
            d += __shfl_xor_sync(0xffffffffu, d, o);
            n += __shfl_xor_sync(0xffffffffu, n, o);
        }
        if (lane == 0) { red[warp] = d; red[8 + warp] = n; }
        __syncthreads();
        if (tid == 0) {
            float dt = 0.f, nt = 0.f;
            #pragma unroll
            for (int w = 0; w < 8; w++) { dt += red[w]; nt += red[8 + w]; }
            float ce   = g_nll / fmaxf(g_valid, 1.f);
            float dice = (nt > 0.f) ? (1.f - dt / fmaxf(nt, 1.f)) : 0.f;
            out[0] = ce + 0.5f * dice;
        }
        __syncthreads();
        // restore scratch invariant (zero on entry) for next graph replay
        if (tid < NC) { g_union[tid] = 0.f; g_inter[tid] = 0.f; g_counts[tid] = 0.f; }
        if (tid == NC) { g_nll = 0.f; g_valid = 0.f; }
        if (tid == 0)  g_ticket = 0;
    }
}

extern "C" void kernel_launch(void* const* d_in, const int* in_sizes, int n_in,
                              void* d_out, int out_size) {
    const float* pred   = (const float*)d_in[0];
    const int*   target = (const int*)d_in[1];
    float*       out    = (float*)d_out;

    cudaFuncSetAttribute(seg_fused, cudaFuncAttributeMaxDynamicSharedMemorySize, SMEM_TOT);
    seg_fused<<<NBLK, TPB, SMEM_TOT>>>(pred, target, out);
}

// round 13
// speedup vs baseline: 1.4406x; 1.0031x over previous
#include <cuda_runtime.h>
#include <cuda_fp16.h>

// SegmentationLoss: ce(ignore=255, mean over valid) + 0.5 * dice
// pred [4,172,256,256] f32, target [4,256,256] i32 -> scalar f32
//
// v7 = v6 (72us) with ONE structural change: 512 persistent blocks x 2
// tiles each (single wave). After tile-0 pass-1, each warp issues
// prefetch.global.L2 for tile-1's entire working set, so DRAM streams
// tile 1 into L2 while tile-0's pass-2/fold (previously DRAM-idle phase)
// executes. Pass-1 / pass-2 / fold code byte-identical to v6.

#define NC   172
#define NCP  (NC/2)             // 86 channel pairs
#define HW   65536
#define NPIX (4 * HW)           // 262144
#define TPB  256
#define NTILE (NPIX / TPB)      // 1024 tiles
#define NBLK  (NTILE / 2)       // 512 blocks, 2 tiles each
#define IGN  255
#define EPSF 1e-7f

// smem byte offsets
#define OFF_TILE   0            // NCP*TPB u16 = 44032
#define OFF_USUM   44032        // 8*NC f32    = 5504
#define OFF_INTER  49536        // NC f32      = 688
#define OFF_CNT    50224        // NC f32      = 688
#define OFF_RED    50912        // 16 f32      = 64
#define OFF_LAST   50976        // int
#define SMEM_TOT   50980

__device__ float g_union[NC];
__device__ float g_inter[NC];
__device__ float g_counts[NC];
__device__ float g_nll;
__device__ float g_valid;
__device__ int   g_ticket;      // zero-init; finisher resets every launch

__device__ __forceinline__ unsigned short pack_e4m3(float hi, float lo) {
    unsigned short r;
    asm("cvt.rn.satfinite.e4m3x2.f32 %0, %1, %2;" : "=h"(r) : "f"(hi), "f"(lo));
    return r;   // byte0 = lo, byte1 = hi
}
__device__ __forceinline__ __half2 unpack_e4m3(unsigned short v) {
    unsigned u;
    asm("cvt.rn.f16x2.e4m3x2 %0, %1;" : "=r"(u) : "h"(v));
    __half2 h;
    *reinterpret_cast<unsigned*>(&h) = u;   // lo half = byte0
    return h;
}

extern __shared__ unsigned char smem_raw[];

__global__ __launch_bounds__(TPB, 4)
void seg_fused(const float* __restrict__ pred, const int* __restrict__ target,
               float* __restrict__ out) {
    unsigned short* tile16 = (unsigned short*)(smem_raw + OFF_TILE);
    float* usum    = (float*)(smem_raw + OFF_USUM);
    float* inter_s = (float*)(smem_raw + OFF_INTER);
    float* cnt_s   = (float*)(smem_raw + OFF_CNT);
    float* red     = (float*)(smem_raw + OFF_RED);
    int*   s_last  = (int*)(smem_raw + OFF_LAST);

    const int tid  = threadIdx.x;
    const int warp = tid >> 5;
    const int lane = tid & 31;

    #pragma unroll 1
    for (int t = 0; t < 2; t++) {
        const int pix0 = (blockIdx.x * 2 + t) * TPB;    // tile-aligned, never crosses batch
        const int b    = pix0 >> 16;
        const int hw   = pix0 & (HW - 1);
        const float* ptr = pred + (size_t)b * NC * HW + hw + tid;

        for (int i = tid; i < NC; i += TPB) { inter_s[i] = 0.f; cnt_s[i] = 0.f; }
        __syncthreads();

        const int  tgt   = target[pix0 + tid];
        const bool valid = (tgt != IGN);

        // ---- pass 1 (byte-identical to v6): 8-wide batches, exp, sum, fp8 stash ----
        float s = 0.f, xt = 0.f;
        #pragma unroll 1
        for (int i = 0; i < 21; i++) {              // 21*8 = 168 channels
            float x[8];
            #pragma unroll
            for (int j = 0; j < 8; j++) x[j] = __ldg(ptr + (size_t)j * HW);
            ptr += (size_t)8 * HW;
            float e[8];
            #pragma unroll
            for (int j = 0; j < 8; j++) {
                e[j] = __expf(x[j]);
                s += e[j];
                if (i * 8 + j == tgt) xt = x[j];
            }
            const int cp = i * 4;
            #pragma unroll
            for (int jp = 0; jp < 4; jp++)
                tile16[(cp + jp) * TPB + tid] = pack_e4m3(e[2*jp+1], e[2*jp]);
        }
        {   // tail: channels 168..171
            float x[4];
            #pragma unroll
            for (int j = 0; j < 4; j++) x[j] = __ldg(ptr + (size_t)j * HW);
            float e[4];
            #pragma unroll
            for (int j = 0; j < 4; j++) {
                e[j] = __expf(x[j]);
                s += e[j];
                if (168 + j == tgt) xt = x[j];
            }
            tile16[84 * TPB + tid] = pack_e4m3(e[1], e[0]);
            tile16[85 * TPB + tid] = pack_e4m3(e[3], e[2]);
        }

        // ---- THE change: prefetch tile 1 into L2 while tile-0 pass-2 runs ----
        if (t == 0 && lane < 8) {
            const int pixN = pix0 + TPB;
            const float* pf = pred + (size_t)(pixN >> 16) * NC * HW
                                   + (pixN & (HW - 1)) + lane * 32;
            #pragma unroll 1
            for (int c = warp; c < NC; c += 8)
                asm volatile("prefetch.global.L2 [%0];" :: "l"(pf + (size_t)c * HW));
        }

        const float inv_s = 1.f / s;
        float nll = valid ? (__logf(s) - xt) : 0.f;
        float vv  = valid ? 1.f : 0.f;

        if (valid) {
            float pt = __expf(xt) * inv_s;          // p at target (fp32 path, exact)
            atomicAdd(&inter_s[tgt], pt);
            atomicAdd(&cnt_s[tgt], 1.f);
        }

        // block-reduce nll & valid count
        #pragma unroll
        for (int o = 16; o; o >>= 1) {
            nll += __shfl_xor_sync(0xffffffffu, nll, o);
            vv  += __shfl_xor_sync(0xffffffffu, vv,  o);
        }
        if (lane == 0) { red[warp] = nll; red[8 + warp] = vv; }

        // ---- pass 2 (byte-identical to v6): per-channel-pair butterflies ----
        const __half2 inv2 = __float2half2_rn(inv_s);
        #pragma unroll 2
        for (int cp = 0; cp < NCP; cp++) {
            __half2 p2 = __hmul2(unpack_e4m3(tile16[cp * TPB + tid]), inv2);
            #pragma unroll
            for (int o = 16; o; o >>= 1) {
                unsigned u = __shfl_xor_sync(0xffffffffu, *reinterpret_cast<unsigned*>(&p2), o);
                p2 = __hadd2(p2, *reinterpret_cast<__half2*>(&u));
            }
            if (lane == 0) {
                float2 f = __half22float2(p2);
                usum[warp * NC + 2*cp]     = f.x;
                usum[warp * NC + 2*cp + 1] = f.y;
            }
        }
        __syncthreads();

        // ---- fold block partials into global accumulators (v6 fold) ----
        if (tid < NC) {
            float u = 0.f;
            #pragma unroll
            for (int w = 0; w < 8; w++) u += usum[w * NC + tid];
            atomicAdd(&g_union[tid], u);
            float iv = inter_s[tid];
            if (iv != 0.f) atomicAdd(&g_inter[tid], iv);
            float cv = cnt_s[tid];
            if (cv != 0.f) atomicAdd(&g_counts[tid], cv);
        } else if (tid == NC) {
            float n = 0.f, v = 0.f;
            #pragma unroll
            for (int w = 0; w < 8; w++) { n += red[w]; v += red[8 + w]; }
            atomicAdd(&g_nll, n);
            atomicAdd(&g_valid, v);
        }
        __syncthreads();    // fold reads done before next tile re-zeroes smem
    }

    // ---- last-CTA finisher (unchanged; NBLK now 512) ----
    __threadfence();
    __syncthreads();
    if (tid == 0) {
        int old = atomicAdd(&g_ticket, 1);
        *s_last = (old == NBLK - 1);
    }
    __syncthreads();
    if (*s_last) {
        __threadfence();    // acquire: all blocks' atomics visible
        float d = 0.f, n = 0.f;
        if (tid < NC) {
            float uni = g_union[tid] + g_counts[tid];
            if (uni > 0.f) { d = (2.f * g_inter[tid] + EPSF) / (uni + EPSF); n = 1.f; }
        }
        #pragma unroll
        for (int o = 16; o; o >>= 1) {
            d += __shfl_xor_sync(0xffffffffu, d, o);
            n += __shfl_xor_sync(0xffffffffu, n, o);
        }
        if (lane == 0) { red[warp] = d; red[8 + warp] = n; }
        __syncthreads();
        if (tid == 0) {
            float dt = 0.f, nt = 0.f;
            #pragma unroll
            for (int w = 0; w < 8; w++) { dt += red[w]; nt += red[8 + w]; }
            float ce   = g_nll / fmaxf(g_valid, 1.f);
            float dice = (nt > 0.f) ? (1.f - dt / fmaxf(nt, 1.f)) : 0.f;
            out[0] = ce + 0.5f * dice;
        }
        __syncthreads();
        // restore scratch invariant (zero on entry) for next graph replay
        if (tid < NC) { g_union[tid] = 0.f; g_inter[tid] = 0.f; g_counts[tid] = 0.f; }
        if (tid == NC) { g_nll = 0.f; g_valid = 0.f; }
        if (tid == 0)  g_ticket = 0;
    }
}

extern "C" void kernel_launch(void* const* d_in, const int* in_sizes, int n_in,
                              void* d_out, int out_size) {
    const float* pred   = (const float*)d_in[0];
    const int*   target = (const int*)d_in[1];
    float*       out    = (float*)d_out;

    cudaFuncSetAttribute(seg_fused, cudaFuncAttributeMaxDynamicSharedMemorySize, SMEM_TOT);
    seg_fused<<<NBLK, TPB, SMEM_TOT>>>(pred, target, out);
}